// round 13
// baseline (speedup 1.0000x reference)
#include <cuda_runtime.h>
#include <math.h>
#include <stdint.h>

#define D_ 256
#define H_ 256
#define B_ 128
#define E_ 128
#define STEPS_ 5
#define NMAX 100352
#define P_ 8            // attention partials per segment
#define ZK 4            // gates split-K factor
#define GP (B_ * 1024)  // one split-K partial: 128 rows x 1024 gate-cols

// ---------------- scratch ----------------
__device__ __align__(16) float g_hfeat[NMAX * H_];
__device__ __align__(16) float g_gpart[ZK * GP];
__device__ float g_h[3][B_ * H_];
__device__ float g_c[3][B_ * H_];
__device__ float g_qstar[B_ * 2 * H_];
__device__ int   g_seg[B_ + 1];
__device__ __align__(16) float g_Wt1[D_ * H_];
__device__ __align__(16) float g_Wt2[H_ * H_];
__device__ float g_att_m[B_ * P_];
__device__ float g_att_d[B_ * P_];
__device__ __align__(16) float g_att_acc[B_ * P_ * H_];
__device__ float g_bcat[3][1024];        // interleaved bias sums (bih+bhh)
// gate-interleaved concatenated [Wih|Whh] hi/lo: row' = 4u+g
#define WO0 0
#define WO1 786432
#define WO2 1310720
#define WTOT 1835008
__device__ __align__(16) float g_Whi[WTOT];
__device__ __align__(16) float g_Wlo[WTOT];
// semaphores (indexed by step -> zeroed once in prep, used once)
__device__ int g_cnt[STEPS_ * 3][16];
__device__ int g_done[STEPS_ * 3];
__device__ int g_acnt[STEPS_ * B_];

__device__ __forceinline__ uint32_t cvt_tf32(float f) {
    uint32_t r;
    asm("cvt.rn.tf32.f32 %0, %1;" : "=r"(r) : "f"(f));
    return r;
}
__device__ __forceinline__ float sigf(float x) { return 1.f / (1.f + expf(-x)); }

#define CP16(dst, src) \
    asm volatile("cp.async.cg.shared.global [%0], [%1], 16;" :: "r"(dst), "l"(src) : "memory")
#define CPCOMMIT() asm volatile("cp.async.commit_group;" ::: "memory")
#define CPWAIT(n)  asm volatile("cp.async.wait_group %0;" :: "n"(n) : "memory")

#define MMA_TF32(d, a, b) \
    asm volatile( \
        "mma.sync.aligned.m16n8k8.row.col.f32.tf32.tf32.f32 " \
        "{%0,%1,%2,%3}, {%4,%5,%6,%7}, {%8,%9}, {%0,%1,%2,%3};" \
        : "+f"((d)[0]), "+f"((d)[1]), "+f"((d)[2]), "+f"((d)[3]) \
        : "r"((a)[0]), "r"((a)[1]), "r"((a)[2]), "r"((a)[3]), \
          "r"((b)[0]), "r"((b)[1]))

// ---------------- prep: seg + transpose + wsplit + bias + zero + counters ----
__global__ __launch_bounds__(256) void k_prep(
    const int* __restrict__ bidx, int N,
    const float* __restrict__ W1, const float* __restrict__ W2,
    const float* __restrict__ Wih0, const float* __restrict__ Whh0,
    const float* __restrict__ Wih1, const float* __restrict__ Whh1,
    const float* __restrict__ Wih2, const float* __restrict__ Whh2,
    const float* __restrict__ bih0, const float* __restrict__ bhh0,
    const float* __restrict__ bih1, const float* __restrict__ bhh1,
    const float* __restrict__ bih2, const float* __restrict__ bhh2)
{
    const int b = blockIdx.x, tid = threadIdx.x;
    if (b == 0) {
        if (tid <= B_) {
            int lo = 0, hi = N;
            while (lo < hi) {
                int mid = (lo + hi) >> 1;
                if (bidx[mid] < tid) lo = mid + 1; else hi = mid;
            }
            g_seg[tid] = lo;
        }
    } else if (b <= 128) {
        __shared__ float t[32][33];
        int t2 = b - 1;
        const float* W = (t2 >= 64) ? W2 : W1;
        float* Wt = (t2 >= 64) ? g_Wt2 : g_Wt1;
        int tile = t2 & 63;
        int bx = (tile & 7) * 32, by = (tile >> 3) * 32;
        int tx = tid & 31, ty0 = tid >> 5;
#pragma unroll
        for (int i = 0; i < 4; i++) {
            int ty = ty0 + 8 * i;
            t[ty][tx] = W[(by + ty) * 256 + bx + tx];
        }
        __syncthreads();
#pragma unroll
        for (int i = 0; i < 4; i++) {
            int ty = ty0 + 8 * i;
            Wt[(bx + ty) * 256 + by + tx] = __uint_as_float(cvt_tf32(t[tx][ty]));
        }
    } else if (b <= 384) {
        int base = (b - 129) * 256 + tid;
        for (int i = base; i < WTOT; i += 65536) {
            int off, K; const float* Wih; const float* Whh;
            if (i < WO1)      { off = WO0; K = 768; Wih = Wih0; Whh = Whh0; }
            else if (i < WO2) { off = WO1; K = 512; Wih = Wih1; Whh = Whh1; }
            else              { off = WO2; K = 512; Wih = Wih2; Whh = Whh2; }
            int j = i - off;
            int n = j / K, k = j - n * K;
            int g = n & 3, u = n >> 2;
            int KW = K - 256;
            float v = (k < KW) ? Wih[(g * 256 + u) * KW + k]
                               : Whh[(g * 256 + u) * 256 + (k - KW)];
            float h = __uint_as_float(cvt_tf32(v));
            g_Whi[i] = h;
            g_Wlo[i] = __uint_as_float(cvt_tf32(v - h));
        }
    } else if (b <= 416) {
        int base = (b - 385) * 256 + tid;  // 8192 threads
        for (int i = base; i < B_ * 2 * H_; i += 8192) g_qstar[i] = 0.f;
        for (int i = base; i < 3 * B_ * H_; i += 8192) {
            (&g_h[0][0])[i] = 0.f;
            (&g_c[0][0])[i] = 0.f;
        }
    } else if (b == 417) {
        for (int e = tid; e < 3 * 1024; e += 256) {
            int l = e >> 10, c = e & 1023, u = c >> 2, g = c & 3;
            const float* bi = (l == 0) ? bih0 : ((l == 1) ? bih1 : bih2);
            const float* bh = (l == 0) ? bhh0 : ((l == 1) ? bhh1 : bhh2);
            g_bcat[l][c] = bi[g * 256 + u] + bh[g * 256 + u];
        }
    } else {
        for (int i = tid; i < STEPS_ * 3 * 16; i += 256) (&g_cnt[0][0])[i] = 0;
        for (int i = tid; i < STEPS_ * 3; i += 256) g_done[i] = 0;
        for (int i = tid; i < STEPS_ * B_; i += 256) g_acnt[i] = 0;
    }
}

// ---------------- fused FNN (R8 512-thread version, known good) --------------
#define FH 0
#define FSA 131072
#define FSB 163840
#define FSMEM 229376

__global__ __launch_bounds__(512) void k_fnn_fused(
    const float* __restrict__ X, const float* __restrict__ W1t,
    const float* __restrict__ W2t, const float* __restrict__ b1,
    const float* __restrict__ b2, float* __restrict__ Cout, int nrows)
{
    extern __shared__ char sm[];
    float* hbuf = (float*)(sm + FH);
    __shared__ float bias1[256];
    __shared__ float bias2[256];

    const int tid  = threadIdx.x;
    const int lane = tid & 31;
    const int warp = tid >> 5;
    const int wm = warp & 3;
    const int wn = warp >> 2;
    const int qr = lane >> 2;
    const int qc = lane & 3;
    const int row0 = blockIdx.x * 128;

    if (tid < 256) bias1[tid] = b1[tid];
    else           bias2[tid - 256] = b2[tid - 256];

    float acc[2][8][4];
#pragma unroll
    for (int mi = 0; mi < 2; mi++)
#pragma unroll
        for (int ni = 0; ni < 8; ni++)
#pragma unroll
            for (int j = 0; j < 4; j++) acc[mi][ni][j] = 0.f;

    auto stage1 = [&](int kc, int s) {
        char* dA = sm + FSA + s * 16384;
        char* dB = sm + FSB + s * 32768;
#pragma unroll
        for (int i = 0; i < 2; i++) {
            int gid = tid + 512 * i;
            int r = gid >> 3, g = gid & 7;
            int gr = row0 + r; if (gr >= nrows) gr = nrows - 1;
            uint32_t dst = (uint32_t)__cvta_generic_to_shared(
                dA + r * 128 + ((g ^ (r & 7)) << 4));
            CP16(dst, X + (size_t)gr * 256 + kc + g * 4);
        }
#pragma unroll
        for (int i = 0; i < 4; i++) {
            int gid = tid + 512 * i;
            int r = gid >> 3, g = gid & 7;
            uint32_t dst = (uint32_t)__cvta_generic_to_shared(
                dB + r * 128 + ((g ^ (r & 7)) << 4));
            CP16(dst, W1t + (size_t)r * 256 + kc + g * 4);
        }
        CPCOMMIT();
    };

    stage1(0, 0);
    for (int c = 0; c < 8; c++) {
        if (c + 1 < 8) { stage1((c + 1) * 32, (c + 1) & 1); CPWAIT(1); }
        else           { CPWAIT(0); }
        __syncthreads();
        const float* As = (const float*)(sm + FSA + (c & 1) * 16384);
        const float* Bs = (const float*)(sm + FSB + (c & 1) * 32768);
#pragma unroll
        for (int ks = 0; ks < 32; ks += 8) {
            const int g0 = ks >> 2;
            uint32_t af[2][4], bf[8][2];
#pragma unroll
            for (int mi = 0; mi < 2; mi++) {
                int ra = wm * 32 + mi * 16 + qr;
                int sw = (ra & 7);
                const float* pa  = As + ra * 32;
                const float* pa8 = pa + 8 * 32;
                af[mi][0] = __float_as_uint(pa [((g0 ^ sw) << 2) + qc]);
                af[mi][1] = __float_as_uint(pa8[((g0 ^ sw) << 2) + qc]);
                af[mi][2] = __float_as_uint(pa [(((g0 + 1) ^ sw) << 2) + qc]);
                af[mi][3] = __float_as_uint(pa8[(((g0 + 1) ^ sw) << 2) + qc]);
            }
#pragma unroll
            for (int ni = 0; ni < 8; ni++) {
                int rb = wn * 64 + ni * 8 + qr;
                int sw = (rb & 7);
                const float* pb = Bs + rb * 32;
                bf[ni][0] = __float_as_uint(pb[((g0 ^ sw) << 2) + qc]);
                bf[ni][1] = __float_as_uint(pb[(((g0 + 1) ^ sw) << 2) + qc]);
            }
#pragma unroll
            for (int mi = 0; mi < 2; mi++)
#pragma unroll
                for (int ni = 0; ni < 8; ni++) MMA_TF32(acc[mi][ni], af[mi], bf[ni]);
        }
        __syncthreads();
    }

#pragma unroll
    for (int mi = 0; mi < 2; mi++) {
        int r = wm * 32 + mi * 16 + qr;
        int sw = (r & 7);
#pragma unroll
        for (int ni = 0; ni < 8; ni++) {
            int cb = wn * 64 + ni * 8 + qc * 2;
            float b0 = bias1[cb], b1v = bias1[cb + 1];
            float v0 = acc[mi][ni][0] + b0, v1 = acc[mi][ni][1] + b1v;
            float v2 = acc[mi][ni][2] + b0, v3 = acc[mi][ni][3] + b1v;
            v0 = (v0 > 0.f) ? v0 : expm1f(v0);
            v1 = (v1 > 0.f) ? v1 : expm1f(v1);
            v2 = (v2 > 0.f) ? v2 : expm1f(v2);
            v3 = (v3 > 0.f) ? v3 : expm1f(v3);
            int gg = cb >> 2, go = cb & 3;
            float* hp  = hbuf + r * 256 + ((gg ^ sw) << 2) + go;
            float* hp8 = hp + 8 * 256;
            hp [0] = __uint_as_float(cvt_tf32(v0));
            hp [1] = __uint_as_float(cvt_tf32(v1));
            hp8[0] = __uint_as_float(cvt_tf32(v2));
            hp8[1] = __uint_as_float(cvt_tf32(v3));
            acc[mi][ni][0] = 0.f; acc[mi][ni][1] = 0.f;
            acc[mi][ni][2] = 0.f; acc[mi][ni][3] = 0.f;
        }
    }
    __syncthreads();

    auto stage2 = [&](int kc, int s) {
        char* dB = sm + FSB + s * 32768;
#pragma unroll
        for (int i = 0; i < 4; i++) {
            int gid = tid + 512 * i;
            int r = gid >> 3, g = gid & 7;
            uint32_t dst = (uint32_t)__cvta_generic_to_shared(
                dB + r * 128 + ((g ^ (r & 7)) << 4));
            CP16(dst, W2t + (size_t)r * 256 + kc + g * 4);
        }
        CPCOMMIT();
    };

    stage2(0, 0);
    for (int c = 0; c < 8; c++) {
        if (c + 1 < 8) { stage2((c + 1) * 32, (c + 1) & 1); CPWAIT(1); }
        else           { CPWAIT(0); }
        __syncthreads();
        const float* Bs = (const float*)(sm + FSB + (c & 1) * 32768);
#pragma unroll
        for (int ks = 0; ks < 32; ks += 8) {
            const int g0 = (c * 32 + ks) >> 2;
            const int g0l = ks >> 2;
            uint32_t af[2][4], bf[8][2];
#pragma unroll
            for (int mi = 0; mi < 2; mi++) {
                int ra = wm * 32 + mi * 16 + qr;
                int sw = (ra & 7);
                const float* pa  = hbuf + ra * 256;
                const float* pa8 = pa + 8 * 256;
                af[mi][0] = __float_as_uint(pa [((g0 ^ sw) << 2) + qc]);
                af[mi][1] = __float_as_uint(pa8[((g0 ^ sw) << 2) + qc]);
                af[mi][2] = __float_as_uint(pa [(((g0 + 1) ^ sw) << 2) + qc]);
                af[mi][3] = __float_as_uint(pa8[(((g0 + 1) ^ sw) << 2) + qc]);
            }
#pragma unroll
            for (int ni = 0; ni < 8; ni++) {
                int rb = wn * 64 + ni * 8 + qr;
                int sw = (rb & 7);
                const float* pb = Bs + rb * 32;
                bf[ni][0] = __float_as_uint(pb[((g0l ^ sw) << 2) + qc]);
                bf[ni][1] = __float_as_uint(pb[(((g0l + 1) ^ sw) << 2) + qc]);
            }
#pragma unroll
            for (int mi = 0; mi < 2; mi++)
#pragma unroll
                for (int ni = 0; ni < 8; ni++) MMA_TF32(acc[mi][ni], af[mi], bf[ni]);
        }
        __syncthreads();
    }

#pragma unroll
    for (int mi = 0; mi < 2; mi++) {
        int r0 = row0 + wm * 32 + mi * 16 + qr;
#pragma unroll
        for (int ni = 0; ni < 8; ni++) {
            int cb = wn * 64 + ni * 8 + qc * 2;
            float b0 = bias2[cb], b1v = bias2[cb + 1];
            if (r0 < nrows)
                *(float2*)(Cout + (size_t)r0 * 256 + cb) =
                    make_float2(acc[mi][ni][0] + b0, acc[mi][ni][1] + b1v);
            if (r0 + 8 < nrows)
                *(float2*)(Cout + (size_t)(r0 + 8) * 256 + cb) =
                    make_float2(acc[mi][ni][2] + b0, acc[mi][ni][3] + b1v);
        }
    }
}

// ---------------- one layer's split-K gate partial (3xTF32 MMA) --------------
// Block tile M=128 x N=64 (gate-interleaved cols), warps 2x4, K chunk 32.
#define GSM_BYTES 98304

template <int K>
__device__ __forceinline__ void lstm_gates_partial(
    float* gsm, const float* xin, const float* hold,
    const float* Whi, const float* Wlo,
    int n0, int z, int tid)
{
    const int KW = K - 256;
    const int lane = tid & 31, warp = tid >> 5;
    const int wm = warp & 1, wn = warp >> 1;
    const int qr = lane >> 2, qc = lane & 3;
    const int kq = K >> 2;
    const int ko = z * kq;
    const int nc = kq >> 5;

    float acc[4][2][4];
#pragma unroll
    for (int mi = 0; mi < 4; mi++)
#pragma unroll
        for (int ni = 0; ni < 2; ni++)
#pragma unroll
            for (int j = 0; j < 4; j++) acc[mi][ni][j] = 0.f;

    float4 ra[4];
    auto ldgA = [&](int kglob) {
#pragma unroll
        for (int i = 0; i < 4; i++) {
            int gid = tid + 256 * i;
            int r = gid >> 3, g = gid & 7;
            int k = kglob + g * 4;
            const float* src; int stride, kk;
            if (k < KW) { src = xin;  stride = KW;  kk = k; }
            else        { src = hold; stride = 256; kk = k - KW; }
            ra[i] = __ldcg((const float4*)(src + (size_t)r * stride + kk));
        }
    };
    auto stsA = [&](int s) {
        float* Ahi = gsm + s * 12288;
        float* Alo = Ahi + 4096;
#pragma unroll
        for (int i = 0; i < 4; i++) {
            int gid = tid + 256 * i;
            int r = gid >> 3, g = gid & 7;
            int off = r * 32 + ((g ^ (r & 7)) << 2);
            float4 v = ra[i];
            float h0 = __uint_as_float(cvt_tf32(v.x));
            float h1 = __uint_as_float(cvt_tf32(v.y));
            float h2 = __uint_as_float(cvt_tf32(v.z));
            float h3 = __uint_as_float(cvt_tf32(v.w));
            Ahi[off + 0] = h0; Ahi[off + 1] = h1;
            Ahi[off + 2] = h2; Ahi[off + 3] = h3;
            Alo[off + 0] = __uint_as_float(cvt_tf32(v.x - h0));
            Alo[off + 1] = __uint_as_float(cvt_tf32(v.y - h1));
            Alo[off + 2] = __uint_as_float(cvt_tf32(v.z - h2));
            Alo[off + 3] = __uint_as_float(cvt_tf32(v.w - h3));
        }
    };
    auto stageB = [&](int kglob, int s) {
        float* Bhi = gsm + s * 12288 + 8192;
        float* Blo = gsm + s * 12288 + 10240;
#pragma unroll
        for (int i = 0; i < 4; i++) {
            int gid = tid + 256 * i;
            int hilo = gid >> 9;
            int rg = gid & 511;
            int r = rg >> 3, g = rg & 7;
            const float* src = (hilo ? Wlo : Whi) + (size_t)(n0 + r) * K + kglob + g * 4;
            float* dstb = hilo ? Blo : Bhi;
            uint32_t dst = (uint32_t)__cvta_generic_to_shared(
                dstb + r * 32 + ((g ^ (r & 7)) << 2));
            CP16(dst, src);
        }
        CPCOMMIT();
    };

    ldgA(ko);
    stageB(ko, 0);
    for (int c = 0; c < nc; c++) {
        const int s = c & 1;
        stsA(s);
        if (c + 1 < nc) {
            ldgA(ko + (c + 1) * 32);
            stageB(ko + (c + 1) * 32, s ^ 1);
            CPWAIT(1);
        } else {
            CPWAIT(0);
        }
        __syncthreads();
        const float* Ahi = gsm + s * 12288;
        const float* Alo = Ahi + 4096;
        const float* Bhi = Ahi + 8192;
        const float* Blo = Ahi + 10240;
#pragma unroll
        for (int ks = 0; ks < 32; ks += 8) {
            const int g0 = ks >> 2;
            uint32_t ah[4][4], al[4][4], bh[2][2], bl[2][2];
#pragma unroll
            for (int mi = 0; mi < 4; mi++) {
                int rr = wm * 64 + mi * 16 + qr;
                int sw = (rr & 7);
                int o0 = rr * 32 + ((g0 ^ sw) << 2) + qc;
                int o1 = rr * 32 + (((g0 + 1) ^ sw) << 2) + qc;
                ah[mi][0] = __float_as_uint(Ahi[o0]);
                ah[mi][1] = __float_as_uint(Ahi[o0 + 256]);
                ah[mi][2] = __float_as_uint(Ahi[o1]);
                ah[mi][3] = __float_as_uint(Ahi[o1 + 256]);
                al[mi][0] = __float_as_uint(Alo[o0]);
                al[mi][1] = __float_as_uint(Alo[o0 + 256]);
                al[mi][2] = __float_as_uint(Alo[o1]);
                al[mi][3] = __float_as_uint(Alo[o1 + 256]);
            }
#pragma unroll
            for (int ni = 0; ni < 2; ni++) {
                int rb = wn * 16 + ni * 8 + qr;
                int sw = (rb & 7);
                int o0 = rb * 32 + ((g0 ^ sw) << 2) + qc;
                int o1 = rb * 32 + (((g0 + 1) ^ sw) << 2) + qc;
                bh[ni][0] = __float_as_uint(Bhi[o0]);
                bh[ni][1] = __float_as_uint(Bhi[o1]);
                bl[ni][0] = __float_as_uint(Blo[o0]);
                bl[ni][1] = __float_as_uint(Blo[o1]);
            }
#pragma unroll
            for (int mi = 0; mi < 4; mi++)
#pragma unroll
                for (int ni = 0; ni < 2; ni++) {
                    MMA_TF32(acc[mi][ni], ah[mi], bh[ni]);
                    MMA_TF32(acc[mi][ni], ah[mi], bl[ni]);
                    MMA_TF32(acc[mi][ni], al[mi], bh[ni]);
                }
        }
        __syncthreads();
    }

    float* gp = g_gpart + (size_t)z * GP;
#pragma unroll
    for (int mi = 0; mi < 4; mi++) {
        int r = wm * 64 + mi * 16 + qr;
#pragma unroll
        for (int ni = 0; ni < 2; ni++) {
            int colb = n0 + wn * 16 + ni * 8 + qc * 2;
            *(float2*)(gp + (size_t)r * 1024 + colb) =
                make_float2(acc[mi][ni][0], acc[mi][ni][1]);
            *(float2*)(gp + (size_t)(r + 8) * 1024 + colb) =
                make_float2(acc[mi][ni][2], acc[mi][ni][3]);
        }
    }
}

// ---------------- fused 3-layer LSTM step (gates + cell update) --------------
// Grid (16 tiles, ZK). Gate-interleaved layout -> last split-K block per tile
// does the cell update for its 16 hidden units; cross-layer sync via counters.
__global__ __launch_bounds__(256) void k_lstm3(int step)
{
    extern __shared__ float gsm[];
    const int tid = threadIdx.x;
    const int t = blockIdx.x, z = blockIdx.y;
    const int n0 = t * 64;
    __shared__ int slast;

    for (int l = 0; l < 3; l++) {
        const float* xin  = (l == 0) ? g_qstar : g_h[l - 1];
        const float* hold = g_h[l];
        if (l == 0)
            lstm_gates_partial<768>(gsm, xin, hold, g_Whi + WO0, g_Wlo + WO0, n0, z, tid);
        else if (l == 1)
            lstm_gates_partial<512>(gsm, xin, hold, g_Whi + WO1, g_Wlo + WO1, n0, z, tid);
        else
            lstm_gates_partial<512>(gsm, xin, hold, g_Whi + WO2, g_Wlo + WO2, n0, z, tid);

        __threadfence();
        __syncthreads();
        if (tid == 0) slast = atomicAdd(&g_cnt[step * 3 + l][t], 1);
        __syncthreads();
        if (slast == ZK - 1) {
            // cell update for units n0/4 .. n0/4+15 (all 128 rows)
#pragma unroll
            for (int rep = 0; rep < 8; rep++) {
                int idx = tid + 256 * rep;
                int r = idx >> 4, ul = idx & 15;
                int col = n0 + ul * 4;
                float4 bv = *(const float4*)&g_bcat[l][col];
                float iv = bv.x, fv = bv.y, gv = bv.z, ov = bv.w;
#pragma unroll
                for (int z2 = 0; z2 < ZK; z2++) {
                    float4 pv = __ldcg((const float4*)(g_gpart + (size_t)z2 * GP + r * 1024 + col));
                    iv += pv.x; fv += pv.y; gv += pv.z; ov += pv.w;
                }
                int u = (n0 >> 2) + ul;
                float cn = sigf(fv) * g_c[l][r * 256 + u] + sigf(iv) * tanhf(gv);
                g_c[l][r * 256 + u] = cn;
                float hn = sigf(ov) * tanhf(cn);
                g_h[l][r * 256 + u] = hn;
                if (l == 2) g_qstar[r * 512 + u] = hn;
            }
            __threadfence();
            __syncthreads();
            if (tid == 0) atomicAdd(&g_done[step * 3 + l], 1);
        }
        if (tid == 0) {
            while (*(volatile int*)&g_done[step * 3 + l] < 16) { }
        }
        __syncthreads();
        __threadfence();
    }
}

// ---------------- attention partials + fused combine -------------------------
__global__ __launch_bounds__(512) void k_attn_part(int step)
{
    const int b = blockIdx.x, part = blockIdx.y, tid = threadIdx.x;
    const int g0 = g_seg[b], g1 = g_seg[b + 1];
    const int len = g1 - g0;
    const int s0 = g0 + (int)(((long long)len * part) / P_);
    const int s1 = g0 + (int)(((long long)len * (part + 1)) / P_);
    const float* hfeat = g_hfeat;

    __shared__ float q_s[256];
    __shared__ float e_s[2][128];
    __shared__ float ws[2][128];
    __shared__ float racc[256];
    __shared__ float red[16];
    __shared__ int alast;
    if (tid < 256) q_s[tid] = g_h[2][b * 256 + tid];
    __syncthreads();

    const int lane = tid & 31, warp = tid >> 5;
    const int col = tid & 255, half = tid >> 8;
    float qreg[8];
#pragma unroll
    for (int k = 0; k < 8; k++) qreg[k] = q_s[lane + 32 * k];

    float acc = 0.f, dpart = 0.f, m = -INFINITY;
    int buf = 0;

    for (int c0 = s0; c0 < s1; c0 += 128, buf ^= 1) {
        const int cnt = min(128, s1 - c0);
#pragma unroll
        for (int i = 0; i < 8; i++) {
            int nl = warp * 8 + i;
            if (nl < cnt) {
                const float* hr = hfeat + (size_t)(c0 + nl) * 256;
                float p = 0.f;
#pragma unroll
                for (int k = 0; k < 8; k++) p += hr[lane + 32 * k] * qreg[k];
#pragma unroll
                for (int off = 16; off; off >>= 1) p += __shfl_xor_sync(0xffffffffu, p, off);
                if (lane == 0) e_s[buf][nl] = p;
            }
        }
        __syncthreads();
        float v = -INFINITY;
#pragma unroll
        for (int j = 0; j < 4; j++) {
            int idx = lane + 32 * j;
            if (idx < cnt) v = fmaxf(v, e_s[buf][idx]);
        }
#pragma unroll
        for (int off = 16; off; off >>= 1)
            v = fmaxf(v, __shfl_xor_sync(0xffffffffu, v, off));
        const float mnew = fmaxf(m, v);
        const float scale = expf(m - mnew);
        acc *= scale; dpart *= scale; m = mnew;
        if (tid < cnt) {
            float wv = expf(e_s[buf][tid] - mnew);
            ws[buf][tid] = wv;
            dpart += wv;
        }
        __syncthreads();
        const int i0 = half * 64;
        const int i1 = min(cnt, i0 + 64);
        const float* bp = hfeat + ((size_t)c0 + i0) * 256 + col;
        const float* wp = ws[buf] + i0;
        if (i1 - i0 == 64) {
            float t0 = 0.f, t1 = 0.f, t2 = 0.f, t3 = 0.f;
#pragma unroll
            for (int i = 0; i < 64; i += 4) {
                t0 += wp[i]     * bp[(size_t)i * 256];
                t1 += wp[i + 1] * bp[(size_t)(i + 1) * 256];
                t2 += wp[i + 2] * bp[(size_t)(i + 2) * 256];
                t3 += wp[i + 3] * bp[(size_t)(i + 3) * 256];
            }
            acc += (t0 + t1) + (t2 + t3);
        } else {
            for (int i = 0; i < i1 - i0; i++) acc += wp[i] * bp[(size_t)i * 256];
        }
    }

    float d = dpart;
#pragma unroll
    for (int off = 16; off; off >>= 1) d += __shfl_xor_sync(0xffffffffu, d, off);
    if (lane == 0) red[warp] = d;
    if (half == 0) racc[col] = acc;
    __syncthreads();
    const int idx = b * P_ + part;
    if (tid == 0) {
        float s = 0.f;
        for (int i = 0; i < 16; i++) s += red[i];
        g_att_d[idx] = s;
        g_att_m[idx] = m;
    }
    if (half == 1) g_att_acc[(size_t)idx * 256 + col] = racc[col] + acc;

    // fused combine: last partial block for segment b merges P_ partials
    __threadfence();
    __syncthreads();
    if (tid == 0) alast = atomicAdd(&g_acnt[step * B_ + b], 1);
    __syncthreads();
    if (alast == P_ - 1) {
        __shared__ float scv[P_];
        __shared__ float sden;
        if (tid == 0) {
            float mm = -INFINITY;
#pragma unroll
            for (int p = 0; p < P_; p++) mm = fmaxf(mm, __ldcg(&g_att_m[b * P_ + p]));
            if (!isfinite(mm)) mm = 0.f;
            float den = 0.f;
#pragma unroll
            for (int p = 0; p < P_; p++) {
                float e = expf(__ldcg(&g_att_m[b * P_ + p]) - mm);
                scv[p] = e;
                den += __ldcg(&g_att_d[b * P_ + p]) * e;
            }
            sden = den + 1e-16f;
        }
        __syncthreads();
        if (tid < 256) {
            float r = 0.f;
#pragma unroll
            for (int p = 0; p < P_; p++)
                r += scv[p] * __ldcg(&g_att_acc[(size_t)(b * P_ + p) * 256 + tid]);
            g_qstar[b * 512 + 256 + tid] = r / sden;
        }
    }
}

// ---------------- output projection ----------------
__global__ void k_out(const float* __restrict__ W, const float* __restrict__ bias,
                      float* __restrict__ out)
{
    int b = blockIdx.x, e = threadIdx.x;
    __shared__ float qs[512];
    qs[e] = g_qstar[b * 512 + e];
    qs[e + 128] = g_qstar[b * 512 + e + 128];
    qs[e + 256] = g_qstar[b * 512 + e + 256];
    qs[e + 384] = g_qstar[b * 512 + e + 384];
    __syncthreads();
    float acc = bias[e];
#pragma unroll 8
    for (int k = 0; k < 512; k++) acc += qs[k] * W[k * E_ + e];
    out[b * E_ + e] = acc;
}

// ---------------- launch ----------------
extern "C" void kernel_launch(void* const* d_in, const int* in_sizes, int n_in,
                              void* d_out, int out_size)
{
    const float* x    = (const float*)d_in[0];
    const int*   bidx = (const int*)d_in[1];
    const float* W1   = (const float*)d_in[2];
    const float* b1   = (const float*)d_in[3];
    const float* W2   = (const float*)d_in[4];
    const float* b2   = (const float*)d_in[5];
    const float* outW = (const float*)d_in[18];
    const float* outb = (const float*)d_in[19];
    float* out = (float*)d_out;

    const int N = in_sizes[0] / D_;

    float *hfeat_p, *wt1_p, *wt2_p;
    cudaGetSymbolAddress((void**)&hfeat_p, g_hfeat);
    cudaGetSymbolAddress((void**)&wt1_p,   g_Wt1);
    cudaGetSymbolAddress((void**)&wt2_p,   g_Wt2);

    cudaFuncSetAttribute(k_fnn_fused, cudaFuncAttributeMaxDynamicSharedMemorySize, FSMEM);
    cudaFuncSetAttribute(k_lstm3, cudaFuncAttributeMaxDynamicSharedMemorySize, GSM_BYTES);

    k_prep<<<419, 256>>>(bidx, N, W1, W2,
                         (const float*)d_in[6],  (const float*)d_in[7],
                         (const float*)d_in[10], (const float*)d_in[11],
                         (const float*)d_in[14], (const float*)d_in[15],
                         (const float*)d_in[8],  (const float*)d_in[9],
                         (const float*)d_in[12], (const float*)d_in[13],
                         (const float*)d_in[16], (const float*)d_in[17]);

    k_fnn_fused<<<(N + 127) / 128, 512, FSMEM>>>(x, wt1_p, wt2_p, b1, b2, hfeat_p, N);

    for (int s = 0; s < STEPS_; s++) {
        dim3 lg(16, ZK);
        k_lstm3<<<lg, 256, GSM_BYTES>>>(s);
        dim3 ag(B_, P_);
        k_attn_part<<<ag, 512>>>(s);
    }
    k_out<<<B_, E_>>>(outW, outb, out);
}

// round 14
// speedup vs baseline: 1.0219x; 1.0219x over previous
#include <cuda_runtime.h>
#include <math.h>
#include <stdint.h>

#define D_ 256
#define H_ 256
#define B_ 128
#define E_ 128
#define STEPS_ 5
#define NMAX 100352
#define P_ 8            // attention partials per segment
#define ZK 4            // gates split-K factor
#define GP (B_ * 1024)

// ---------------- scratch ----------------
__device__ __align__(16) float g_hfeat[NMAX * H_];
__device__ __align__(16) float g_gpart[ZK * GP];
__device__ float g_hbuf[2][3][B_ * H_];
__device__ float g_c[3][B_ * H_];
__device__ float g_qstar[B_ * 2 * H_];
__device__ int   g_seg[B_ + 1];
__device__ __align__(16) float g_Wt1[D_ * H_];
__device__ __align__(16) float g_Wt2[H_ * H_];
__device__ float g_att_m[B_ * P_];
__device__ float g_att_d[B_ * P_];
__device__ __align__(16) float g_att_acc[B_ * P_ * H_];
__device__ float g_bcat[3][1024];
// gate-interleaved concatenated [Wih|Whh] hi/lo: row' = 4u+g
#define WO0 0
#define WO1 786432
#define WO2 1310720
#define WTOT 1835008
__device__ __align__(16) float g_Whi[WTOT];
__device__ __align__(16) float g_Wlo[WTOT];
__device__ int g_cnt[STEPS_ * 3][16];    // split-K arrival counters

__device__ __forceinline__ uint32_t cvt_tf32(float f) {
    uint32_t r;
    asm("cvt.rn.tf32.f32 %0, %1;" : "=r"(r) : "f"(f));
    return r;
}
__device__ __forceinline__ float sigf(float x) { return 1.f / (1.f + expf(-x)); }

#define CP16(dst, src) \
    asm volatile("cp.async.cg.shared.global [%0], [%1], 16;" :: "r"(dst), "l"(src) : "memory")
#define CPCOMMIT() asm volatile("cp.async.commit_group;" ::: "memory")
#define CPWAIT(n)  asm volatile("cp.async.wait_group %0;" :: "n"(n) : "memory")

#define MMA_TF32(d, a, b) \
    asm volatile( \
        "mma.sync.aligned.m16n8k8.row.col.f32.tf32.tf32.f32 " \
        "{%0,%1,%2,%3}, {%4,%5,%6,%7}, {%8,%9}, {%0,%1,%2,%3};" \
        : "+f"((d)[0]), "+f"((d)[1]), "+f"((d)[2]), "+f"((d)[3]) \
        : "r"((a)[0]), "r"((a)[1]), "r"((a)[2]), "r"((a)[3]), \
          "r"((b)[0]), "r"((b)[1]))

// ---------------- prep (verified R12): seg+transpose+wsplit+bias+zero --------
__global__ __launch_bounds__(256) void k_prep(
    const int* __restrict__ bidx, int N,
    const float* __restrict__ W1, const float* __restrict__ W2,
    const float* __restrict__ Wih0, const float* __restrict__ Whh0,
    const float* __restrict__ Wih1, const float* __restrict__ Whh1,
    const float* __restrict__ Wih2, const float* __restrict__ Whh2,
    const float* __restrict__ bih0, const float* __restrict__ bhh0,
    const float* __restrict__ bih1, const float* __restrict__ bhh1,
    const float* __restrict__ bih2, const float* __restrict__ bhh2)
{
    const int b = blockIdx.x, tid = threadIdx.x;
    if (b == 0) {
        if (tid <= B_) {
            int lo = 0, hi = N;
            while (lo < hi) {
                int mid = (lo + hi) >> 1;
                if (bidx[mid] < tid) lo = mid + 1; else hi = mid;
            }
            g_seg[tid] = lo;
        }
    } else if (b <= 128) {
        __shared__ float t[32][33];
        int t2 = b - 1;
        const float* W = (t2 >= 64) ? W2 : W1;
        float* Wt = (t2 >= 64) ? g_Wt2 : g_Wt1;
        int tile = t2 & 63;
        int bx = (tile & 7) * 32, by = (tile >> 3) * 32;
        int tx = tid & 31, ty0 = tid >> 5;
#pragma unroll
        for (int i = 0; i < 4; i++) {
            int ty = ty0 + 8 * i;
            t[ty][tx] = W[(by + ty) * 256 + bx + tx];
        }
        __syncthreads();
#pragma unroll
        for (int i = 0; i < 4; i++) {
            int ty = ty0 + 8 * i;
            Wt[(bx + ty) * 256 + by + tx] = __uint_as_float(cvt_tf32(t[tx][ty]));
        }
    } else if (b <= 384) {
        int base = (b - 129) * 256 + tid;
        for (int i = base; i < WTOT; i += 65536) {
            int off, K; const float* Wih; const float* Whh;
            if (i < WO1)      { off = WO0; K = 768; Wih = Wih0; Whh = Whh0; }
            else if (i < WO2) { off = WO1; K = 512; Wih = Wih1; Whh = Whh1; }
            else              { off = WO2; K = 512; Wih = Wih2; Whh = Whh2; }
            int j = i - off;
            int n = j / K, k = j - n * K;
            int g = n & 3, u = n >> 2;
            int KW = K - 256;
            float v = (k < KW) ? Wih[(g * 256 + u) * KW + k]
                               : Whh[(g * 256 + u) * 256 + (k - KW)];
            float h = __uint_as_float(cvt_tf32(v));
            g_Whi[i] = h;
            g_Wlo[i] = __uint_as_float(cvt_tf32(v - h));
        }
    } else if (b <= 416) {
        int base = (b - 385) * 256 + tid;  // 8192 threads
        for (int i = base; i < B_ * 2 * H_; i += 8192) g_qstar[i] = 0.f;
        for (int i = base; i < 3 * B_ * H_; i += 8192) {
            g_hbuf[0][0][i] = 0.f;
            g_hbuf[1][0][i] = 0.f;
            g_c[0][i] = 0.f;
        }
    } else if (b == 417) {
        for (int e = tid; e < 3 * 1024; e += 256) {
            int l = e >> 10, c = e & 1023, u = c >> 2, g = c & 3;
            const float* bi = (l == 0) ? bih0 : ((l == 1) ? bih1 : bih2);
            const float* bh = (l == 0) ? bhh0 : ((l == 1) ? bhh1 : bhh2);
            g_bcat[l][c] = bi[g * 256 + u] + bh[g * 256 + u];
        }
    } else {
        for (int i = tid; i < STEPS_ * 3 * 16; i += 256) (&g_cnt[0][0])[i] = 0;
    }
}

// ---------------- fused FNN (R8 512-thread version, known good) --------------
#define FH 0
#define FSA 131072
#define FSB 163840
#define FSMEM 229376

__global__ __launch_bounds__(512) void k_fnn_fused(
    const float* __restrict__ X, const float* __restrict__ W1t,
    const float* __restrict__ W2t, const float* __restrict__ b1,
    const float* __restrict__ b2, float* __restrict__ Cout, int nrows)
{
    extern __shared__ char sm[];
    float* hbuf = (float*)(sm + FH);
    __shared__ float bias1[256];
    __shared__ float bias2[256];

    const int tid  = threadIdx.x;
    const int lane = tid & 31;
    const int warp = tid >> 5;
    const int wm = warp & 3;
    const int wn = warp >> 2;
    const int qr = lane >> 2;
    const int qc = lane & 3;
    const int row0 = blockIdx.x * 128;

    if (tid < 256) bias1[tid] = b1[tid];
    else           bias2[tid - 256] = b2[tid - 256];

    float acc[2][8][4];
#pragma unroll
    for (int mi = 0; mi < 2; mi++)
#pragma unroll
        for (int ni = 0; ni < 8; ni++)
#pragma unroll
            for (int j = 0; j < 4; j++) acc[mi][ni][j] = 0.f;

    auto stage1 = [&](int kc, int s) {
        char* dA = sm + FSA + s * 16384;
        char* dB = sm + FSB + s * 32768;
#pragma unroll
        for (int i = 0; i < 2; i++) {
            int gid = tid + 512 * i;
            int r = gid >> 3, g = gid & 7;
            int gr = row0 + r; if (gr >= nrows) gr = nrows - 1;
            uint32_t dst = (uint32_t)__cvta_generic_to_shared(
                dA + r * 128 + ((g ^ (r & 7)) << 4));
            CP16(dst, X + (size_t)gr * 256 + kc + g * 4);
        }
#pragma unroll
        for (int i = 0; i < 4; i++) {
            int gid = tid + 512 * i;
            int r = gid >> 3, g = gid & 7;
            uint32_t dst = (uint32_t)__cvta_generic_to_shared(
                dB + r * 128 + ((g ^ (r & 7)) << 4));
            CP16(dst, W1t + (size_t)r * 256 + kc + g * 4);
        }
        CPCOMMIT();
    };

    stage1(0, 0);
    for (int c = 0; c < 8; c++) {
        if (c + 1 < 8) { stage1((c + 1) * 32, (c + 1) & 1); CPWAIT(1); }
        else           { CPWAIT(0); }
        __syncthreads();
        const float* As = (const float*)(sm + FSA + (c & 1) * 16384);
        const float* Bs = (const float*)(sm + FSB + (c & 1) * 32768);
#pragma unroll
        for (int ks = 0; ks < 32; ks += 8) {
            const int g0 = ks >> 2;
            uint32_t af[2][4], bf[8][2];
#pragma unroll
            for (int mi = 0; mi < 2; mi++) {
                int ra = wm * 32 + mi * 16 + qr;
                int sw = (ra & 7);
                const float* pa  = As + ra * 32;
                const float* pa8 = pa + 8 * 32;
                af[mi][0] = __float_as_uint(pa [((g0 ^ sw) << 2) + qc]);
                af[mi][1] = __float_as_uint(pa8[((g0 ^ sw) << 2) + qc]);
                af[mi][2] = __float_as_uint(pa [(((g0 + 1) ^ sw) << 2) + qc]);
                af[mi][3] = __float_as_uint(pa8[(((g0 + 1) ^ sw) << 2) + qc]);
            }
#pragma unroll
            for (int ni = 0; ni < 8; ni++) {
                int rb = wn * 64 + ni * 8 + qr;
                int sw = (rb & 7);
                const float* pb = Bs + rb * 32;
                bf[ni][0] = __float_as_uint(pb[((g0 ^ sw) << 2) + qc]);
                bf[ni][1] = __float_as_uint(pb[(((g0 + 1) ^ sw) << 2) + qc]);
            }
#pragma unroll
            for (int mi = 0; mi < 2; mi++)
#pragma unroll
                for (int ni = 0; ni < 8; ni++) MMA_TF32(acc[mi][ni], af[mi], bf[ni]);
        }
        __syncthreads();
    }

#pragma unroll
    for (int mi = 0; mi < 2; mi++) {
        int r = wm * 32 + mi * 16 + qr;
        int sw = (r & 7);
#pragma unroll
        for (int ni = 0; ni < 8; ni++) {
            int cb = wn * 64 + ni * 8 + qc * 2;
            float b0 = bias1[cb], b1v = bias1[cb + 1];
            float v0 = acc[mi][ni][0] + b0, v1 = acc[mi][ni][1] + b1v;
            float v2 = acc[mi][ni][2] + b0, v3 = acc[mi][ni][3] + b1v;
            v0 = (v0 > 0.f) ? v0 : expm1f(v0);
            v1 = (v1 > 0.f) ? v1 : expm1f(v1);
            v2 = (v2 > 0.f) ? v2 : expm1f(v2);
            v3 = (v3 > 0.f) ? v3 : expm1f(v3);
            int gg = cb >> 2, go = cb & 3;
            float* hp  = hbuf + r * 256 + ((gg ^ sw) << 2) + go;
            float* hp8 = hp + 8 * 256;
            hp [0] = __uint_as_float(cvt_tf32(v0));
            hp [1] = __uint_as_float(cvt_tf32(v1));
            hp8[0] = __uint_as_float(cvt_tf32(v2));
            hp8[1] = __uint_as_float(cvt_tf32(v3));
            acc[mi][ni][0] = 0.f; acc[mi][ni][1] = 0.f;
            acc[mi][ni][2] = 0.f; acc[mi][ni][3] = 0.f;
        }
    }
    __syncthreads();

    auto stage2 = [&](int kc, int s) {
        char* dB = sm + FSB + s * 32768;
#pragma unroll
        for (int i = 0; i < 4; i++) {
            int gid = tid + 512 * i;
            int r = gid >> 3, g = gid & 7;
            uint32_t dst = (uint32_t)__cvta_generic_to_shared(
                dB + r * 128 + ((g ^ (r & 7)) << 4));
            CP16(dst, W2t + (size_t)r * 256 + kc + g * 4);
        }
        CPCOMMIT();
    };

    stage2(0, 0);
    for (int c = 0; c < 8; c++) {
        if (c + 1 < 8) { stage2((c + 1) * 32, (c + 1) & 1); CPWAIT(1); }
        else           { CPWAIT(0); }
        __syncthreads();
        const float* Bs = (const float*)(sm + FSB + (c & 1) * 32768);
#pragma unroll
        for (int ks = 0; ks < 32; ks += 8) {
            const int g0 = (c * 32 + ks) >> 2;
            const int g0l = ks >> 2;
            uint32_t af[2][4], bf[8][2];
#pragma unroll
            for (int mi = 0; mi < 2; mi++) {
                int ra = wm * 32 + mi * 16 + qr;
                int sw = (ra & 7);
                const float* pa  = hbuf + ra * 256;
                const float* pa8 = pa + 8 * 256;
                af[mi][0] = __float_as_uint(pa [((g0 ^ sw) << 2) + qc]);
                af[mi][1] = __float_as_uint(pa8[((g0 ^ sw) << 2) + qc]);
                af[mi][2] = __float_as_uint(pa [(((g0 + 1) ^ sw) << 2) + qc]);
                af[mi][3] = __float_as_uint(pa8[(((g0 + 1) ^ sw) << 2) + qc]);
            }
#pragma unroll
            for (int ni = 0; ni < 8; ni++) {
                int rb = wn * 64 + ni * 8 + qr;
                int sw = (rb & 7);
                const float* pb = Bs + rb * 32;
                bf[ni][0] = __float_as_uint(pb[((g0l ^ sw) << 2) + qc]);
                bf[ni][1] = __float_as_uint(pb[(((g0l + 1) ^ sw) << 2) + qc]);
            }
#pragma unroll
            for (int mi = 0; mi < 2; mi++)
#pragma unroll
                for (int ni = 0; ni < 8; ni++) MMA_TF32(acc[mi][ni], af[mi], bf[ni]);
        }
        __syncthreads();
    }

#pragma unroll
    for (int mi = 0; mi < 2; mi++) {
        int r0 = row0 + wm * 32 + mi * 16 + qr;
#pragma unroll
        for (int ni = 0; ni < 8; ni++) {
            int cb = wn * 64 + ni * 8 + qc * 2;
            float b0 = bias2[cb], b1v = bias2[cb + 1];
            if (r0 < nrows)
                *(float2*)(Cout + (size_t)r0 * 256 + cb) =
                    make_float2(acc[mi][ni][0] + b0, acc[mi][ni][1] + b1v);
            if (r0 + 8 < nrows)
                *(float2*)(Cout + (size_t)(r0 + 8) * 256 + cb) =
                    make_float2(acc[mi][ni][2] + b0, acc[mi][ni][3] + b1v);
        }
    }
}

// ---------------- LSTM layer: 3xTF32 gates + fused cell update ---------------
// Grid (16, ZK), 256 thr. Gate-interleaved cols. Last split-K block per tile
// sums partials + cell-updates its 16 hidden units (ping-pong h buffers).
#define GSM_BYTES 98304

template <int K>
__global__ __launch_bounds__(256) void k_lstm_layer(
    const float* __restrict__ xin, const float* __restrict__ hold,
    const float* __restrict__ Whi, const float* __restrict__ Wlo,
    const float* __restrict__ bcat, float* __restrict__ c,
    float* __restrict__ hnew, float* __restrict__ qdst, int* __restrict__ cnt)
{
    extern __shared__ float gsm[];
    const int KW = K - 256;
    const int tid = threadIdx.x;
    const int lane = tid & 31, warp = tid >> 5;
    const int wm = warp & 1, wn = warp >> 1;
    const int qr = lane >> 2, qc = lane & 3;
    const int t = blockIdx.x, z = blockIdx.y;
    const int n0 = t * 64;
    const int kq = K >> 2;
    const int ko = z * kq;
    const int nc = kq >> 5;
    __shared__ int slast;

    float acc[4][2][4];
#pragma unroll
    for (int mi = 0; mi < 4; mi++)
#pragma unroll
        for (int ni = 0; ni < 2; ni++)
#pragma unroll
            for (int j = 0; j < 4; j++) acc[mi][ni][j] = 0.f;

    float4 ra[4];
    auto ldgA = [&](int kglob) {
#pragma unroll
        for (int i = 0; i < 4; i++) {
            int gid = tid + 256 * i;
            int r = gid >> 3, g = gid & 7;
            int k = kglob + g * 4;
            const float* src; int stride, kk;
            if (k < KW) { src = xin;  stride = KW;  kk = k; }
            else        { src = hold; stride = 256; kk = k - KW; }
            ra[i] = *(const float4*)(src + (size_t)r * stride + kk);
        }
    };
    auto stsA = [&](int s) {
        float* Ahi = gsm + s * 12288;
        float* Alo = Ahi + 4096;
#pragma unroll
        for (int i = 0; i < 4; i++) {
            int gid = tid + 256 * i;
            int r = gid >> 3, g = gid & 7;
            int off = r * 32 + ((g ^ (r & 7)) << 2);
            float4 v = ra[i];
            float h0 = __uint_as_float(cvt_tf32(v.x));
            float h1 = __uint_as_float(cvt_tf32(v.y));
            float h2 = __uint_as_float(cvt_tf32(v.z));
            float h3 = __uint_as_float(cvt_tf32(v.w));
            Ahi[off + 0] = h0; Ahi[off + 1] = h1;
            Ahi[off + 2] = h2; Ahi[off + 3] = h3;
            Alo[off + 0] = __uint_as_float(cvt_tf32(v.x - h0));
            Alo[off + 1] = __uint_as_float(cvt_tf32(v.y - h1));
            Alo[off + 2] = __uint_as_float(cvt_tf32(v.z - h2));
            Alo[off + 3] = __uint_as_float(cvt_tf32(v.w - h3));
        }
    };
    auto stageB = [&](int kglob, int s) {
        float* Bhi = gsm + s * 12288 + 8192;
        float* Blo = gsm + s * 12288 + 10240;
#pragma unroll
        for (int i = 0; i < 4; i++) {
            int gid = tid + 256 * i;
            int hilo = gid >> 9;
            int rg = gid & 511;
            int r = rg >> 3, g = rg & 7;
            const float* src = (hilo ? Wlo : Whi) + (size_t)(n0 + r) * K + kglob + g * 4;
            float* dstb = hilo ? Blo : Bhi;
            uint32_t dst = (uint32_t)__cvta_generic_to_shared(
                dstb + r * 32 + ((g ^ (r & 7)) << 2));
            CP16(dst, src);
        }
        CPCOMMIT();
    };

    ldgA(ko);
    stageB(ko, 0);
    for (int ch = 0; ch < nc; ch++) {
        const int s = ch & 1;
        stsA(s);
        if (ch + 1 < nc) {
            ldgA(ko + (ch + 1) * 32);
            stageB(ko + (ch + 1) * 32, s ^ 1);
            CPWAIT(1);
        } else {
            CPWAIT(0);
        }
        __syncthreads();
        const float* Ahi = gsm + s * 12288;
        const float* Alo = Ahi + 4096;
        const float* Bhi = Ahi + 8192;
        const float* Blo = Ahi + 10240;
#pragma unroll
        for (int ks = 0; ks < 32; ks += 8) {
            const int g0 = ks >> 2;
            uint32_t ah[4][4], al[4][4], bh[2][2], bl[2][2];
#pragma unroll
            for (int mi = 0; mi < 4; mi++) {
                int rr = wm * 64 + mi * 16 + qr;
                int sw = (rr & 7);
                int o0 = rr * 32 + ((g0 ^ sw) << 2) + qc;
                int o1 = rr * 32 + (((g0 + 1) ^ sw) << 2) + qc;
                ah[mi][0] = __float_as_uint(Ahi[o0]);
                ah[mi][1] = __float_as_uint(Ahi[o0 + 256]);
                ah[mi][2] = __float_as_uint(Ahi[o1]);
                ah[mi][3] = __float_as_uint(Ahi[o1 + 256]);
                al[mi][0] = __float_as_uint(Alo[o0]);
                al[mi][1] = __float_as_uint(Alo[o0 + 256]);
                al[mi][2] = __float_as_uint(Alo[o1]);
                al[mi][3] = __float_as_uint(Alo[o1 + 256]);
            }
#pragma unroll
            for (int ni = 0; ni < 2; ni++) {
                int rb = wn * 16 + ni * 8 + qr;
                int sw = (rb & 7);
                int o0 = rb * 32 + ((g0 ^ sw) << 2) + qc;
                int o1 = rb * 32 + (((g0 + 1) ^ sw) << 2) + qc;
                bh[ni][0] = __float_as_uint(Bhi[o0]);
                bh[ni][1] = __float_as_uint(Bhi[o1]);
                bl[ni][0] = __float_as_uint(Blo[o0]);
                bl[ni][1] = __float_as_uint(Blo[o1]);
            }
#pragma unroll
            for (int mi = 0; mi < 4; mi++)
#pragma unroll
                for (int ni = 0; ni < 2; ni++) {
                    MMA_TF32(acc[mi][ni], ah[mi], bh[ni]);
                    MMA_TF32(acc[mi][ni], ah[mi], bl[ni]);
                    MMA_TF32(acc[mi][ni], al[mi], bh[ni]);
                }
        }
        __syncthreads();
    }

    float* gp = g_gpart + (size_t)z * GP;
#pragma unroll
    for (int mi = 0; mi < 4; mi++) {
        int r = wm * 64 + mi * 16 + qr;
#pragma unroll
        for (int ni = 0; ni < 2; ni++) {
            int colb = n0 + wn * 16 + ni * 8 + qc * 2;
            *(float2*)(gp + (size_t)r * 1024 + colb) =
                make_float2(acc[mi][ni][0], acc[mi][ni][1]);
            *(float2*)(gp + (size_t)(r + 8) * 1024 + colb) =
                make_float2(acc[mi][ni][2], acc[mi][ni][3]);
        }
    }

    // split-K last-arriving block does the cell update for this tile
    __threadfence();
    __syncthreads();
    if (tid == 0) slast = atomicAdd(&cnt[t], 1);
    __syncthreads();
    if (slast == ZK - 1) {
#pragma unroll
        for (int rep = 0; rep < 8; rep++) {
            int idx = tid + 256 * rep;
            int r = idx >> 4, ul = idx & 15;
            int col = n0 + ul * 4;
            float4 bv = *(const float4*)(bcat + col);
            float iv = bv.x, fv = bv.y, gv = bv.z, ov = bv.w;
#pragma unroll
            for (int z2 = 0; z2 < ZK; z2++) {
                float4 pv = __ldcg((const float4*)(g_gpart + (size_t)z2 * GP + r * 1024 + col));
                iv += pv.x; fv += pv.y; gv += pv.z; ov += pv.w;
            }
            int u = (n0 >> 2) + ul;
            float cn = sigf(fv) * c[r * 256 + u] + sigf(iv) * tanhf(gv);
            c[r * 256 + u] = cn;
            float hn = sigf(ov) * tanhf(cn);
            hnew[r * 256 + u] = hn;
            if (qdst) qdst[r * 512 + u] = hn;
        }
    }
}

// ---------------- attention partials (R11, known good) -----------------------
__global__ __launch_bounds__(512) void k_attn_part(
    const float* __restrict__ hfeat, const float* __restrict__ q)
{
    const int b = blockIdx.x, part = blockIdx.y, tid = threadIdx.x;
    const int g0 = g_seg[b], g1 = g_seg[b + 1];
    const int len = g1 - g0;
    const int s0 = g0 + (int)(((long long)len * part) / P_);
    const int s1 = g0 + (int)(((long long)len * (part + 1)) / P_);

    __shared__ float q_s[256];
    __shared__ float e_s[2][128];
    __shared__ float ws[2][128];
    __shared__ float racc[256];
    __shared__ float red[16];
    if (tid < 256) q_s[tid] = q[b * 256 + tid];
    __syncthreads();

    const int lane = tid & 31, warp = tid >> 5;
    const int col = tid & 255, half = tid >> 8;
    float qreg[8];
#pragma unroll
    for (int k = 0; k < 8; k++) qreg[k] = q_s[lane + 32 * k];

    float acc = 0.f, dpart = 0.f, m = -INFINITY;
    int buf = 0;

    for (int c0 = s0; c0 < s1; c0 += 128, buf ^= 1) {
        const int cnt = min(128, s1 - c0);
#pragma unroll
        for (int i = 0; i < 8; i++) {
            int nl = warp * 8 + i;
            if (nl < cnt) {
                const float* hr = hfeat + (size_t)(c0 + nl) * 256;
                float p = 0.f;
#pragma unroll
                for (int k = 0; k < 8; k++) p += hr[lane + 32 * k] * qreg[k];
#pragma unroll
                for (int off = 16; off; off >>= 1) p += __shfl_xor_sync(0xffffffffu, p, off);
                if (lane == 0) e_s[buf][nl] = p;
            }
        }
        __syncthreads();
        float v = -INFINITY;
#pragma unroll
        for (int j = 0; j < 4; j++) {
            int idx = lane + 32 * j;
            if (idx < cnt) v = fmaxf(v, e_s[buf][idx]);
        }
#pragma unroll
        for (int off = 16; off; off >>= 1)
            v = fmaxf(v, __shfl_xor_sync(0xffffffffu, v, off));
        const float mnew = fmaxf(m, v);
        const float scale = expf(m - mnew);
        acc *= scale; dpart *= scale; m = mnew;
        if (tid < cnt) {
            float wv = expf(e_s[buf][tid] - mnew);
            ws[buf][tid] = wv;
            dpart += wv;
        }
        __syncthreads();
        const int i0 = half * 64;
        const int i1 = min(cnt, i0 + 64);
        const float* bp = hfeat + ((size_t)c0 + i0) * 256 + col;
        const float* wp = ws[buf] + i0;
        if (i1 - i0 == 64) {
            float t0 = 0.f, t1 = 0.f, t2 = 0.f, t3 = 0.f;
#pragma unroll
            for (int i = 0; i < 64; i += 4) {
                t0 += wp[i]     * bp[(size_t)i * 256];
                t1 += wp[i + 1] * bp[(size_t)(i + 1) * 256];
                t2 += wp[i + 2] * bp[(size_t)(i + 2) * 256];
                t3 += wp[i + 3] * bp[(size_t)(i + 3) * 256];
            }
            acc += (t0 + t1) + (t2 + t3);
        } else {
            for (int i = 0; i < i1 - i0; i++) acc += wp[i] * bp[(size_t)i * 256];
        }
    }

    float d = dpart;
#pragma unroll
    for (int off = 16; off; off >>= 1) d += __shfl_xor_sync(0xffffffffu, d, off);
    if (lane == 0) red[warp] = d;
    if (half == 0) racc[col] = acc;
    __syncthreads();
    const int idx = b * P_ + part;
    if (tid == 0) {
        float s = 0.f;
        for (int i = 0; i < 16; i++) s += red[i];
        g_att_d[idx] = s;
        g_att_m[idx] = m;
    }
    if (half == 1) g_att_acc[(size_t)idx * 256 + col] = racc[col] + acc;
}

// ---------------- attention combine ----------------
__global__ __launch_bounds__(256) void k_attn_comb(float* __restrict__ qstar)
{
    const int b = blockIdx.x, col = threadIdx.x;
    __shared__ float sc[P_];
    __shared__ float sdenom;
    if (col == 0) {
        float m = -INFINITY;
#pragma unroll
        for (int p = 0; p < P_; p++) m = fmaxf(m, g_att_m[b * P_ + p]);
        if (!isfinite(m)) m = 0.f;
        float denom = 0.f;
#pragma unroll
        for (int p = 0; p < P_; p++) {
            float e = expf(g_att_m[b * P_ + p] - m);
            sc[p] = e;
            denom += g_att_d[b * P_ + p] * e;
        }
        sdenom = denom + 1e-16f;
    }
    __syncthreads();
    float r = 0.f;
#pragma unroll
    for (int p = 0; p < P_; p++)
        r += sc[p] * g_att_acc[(size_t)(b * P_ + p) * 256 + col];
    qstar[b * 2 * H_ + 256 + col] = r / sdenom;
}

// ---------------- output projection ----------------
__global__ void k_out(const float* __restrict__ qstar, const float* __restrict__ W,
                      const float* __restrict__ bias, float* __restrict__ out)
{
    int b = blockIdx.x, e = threadIdx.x;
    __shared__ float qs[512];
    qs[e] = qstar[b * 512 + e];
    qs[e + 128] = qstar[b * 512 + e + 128];
    qs[e + 256] = qstar[b * 512 + e + 256];
    qs[e + 384] = qstar[b * 512 + e + 384];
    __syncthreads();
    float acc = bias[e];
#pragma unroll 8
    for (int k = 0; k < 512; k++) acc += qs[k] * W[k * E_ + e];
    out[b * E_ + e] = acc;
}

// ---------------- launch ----------------
extern "C" void kernel_launch(void* const* d_in, const int* in_sizes, int n_in,
                              void* d_out, int out_size)
{
    const float* x    = (const float*)d_in[0];
    const int*   bidx = (const int*)d_in[1];
    const float* W1   = (const float*)d_in[2];
    const float* b1   = (const float*)d_in[3];
    const float* W2   = (const float*)d_in[4];
    const float* b2   = (const float*)d_in[5];
    const float* outW = (const float*)d_in[18];
    const float* outb = (const float*)d_in[19];
    float* out = (float*)d_out;

    const int N = in_sizes[0] / D_;

    float *hfeat_p, *hbuf_p, *c_p, *qstar_p, *wt1_p, *wt2_p, *whi_p, *wlo_p, *bcat_p;
    int* cnt_p;
    cudaGetSymbolAddress((void**)&hfeat_p, g_hfeat);
    cudaGetSymbolAddress((void**)&hbuf_p,  g_hbuf);
    cudaGetSymbolAddress((void**)&c_p,     g_c);
    cudaGetSymbolAddress((void**)&qstar_p, g_qstar);
    cudaGetSymbolAddress((void**)&wt1_p,   g_Wt1);
    cudaGetSymbolAddress((void**)&wt2_p,   g_Wt2);
    cudaGetSymbolAddress((void**)&whi_p,   g_Whi);
    cudaGetSymbolAddress((void**)&wlo_p,   g_Wlo);
    cudaGetSymbolAddress((void**)&bcat_p,  g_bcat);
    cudaGetSymbolAddress((void**)&cnt_p,   g_cnt);

    cudaFuncSetAttribute(k_fnn_fused, cudaFuncAttributeMaxDynamicSharedMemorySize, FSMEM);
    cudaFuncSetAttribute(k_lstm_layer<768>, cudaFuncAttributeMaxDynamicSharedMemorySize, GSM_BYTES);
    cudaFuncSetAttribute(k_lstm_layer<512>, cudaFuncAttributeMaxDynamicSharedMemorySize, GSM_BYTES);

    k_prep<<<419, 256>>>(bidx, N, W1, W2,
                         (const float*)d_in[6],  (const float*)d_in[7],
                         (const float*)d_in[10], (const float*)d_in[11],
                         (const float*)d_in[14], (const float*)d_in[15],
                         (const float*)d_in[8],  (const float*)d_in[9],
                         (const float*)d_in[12], (const float*)d_in[13],
                         (const float*)d_in[16], (const float*)d_in[17]);

    k_fnn_fused<<<(N + 127) / 128, 512, FSMEM>>>(x, wt1_p, wt2_p, b1, b2, hfeat_p, N);

    const int woff[3] = {WO0, WO1, WO2};
    for (int s = 0; s < STEPS_; s++) {
        float* hold = hbuf_p + (size_t)(s & 1) * 3 * B_ * H_;
        float* hnew = hbuf_p + (size_t)((s & 1) ^ 1) * 3 * B_ * H_;
        for (int l = 0; l < 3; l++) {
            const float* xin = (l == 0) ? (const float*)qstar_p
                                        : (const float*)(hnew + (size_t)(l - 1) * B_ * H_);
            dim3 gg(16, ZK);
            float* qdst = (l == 2) ? qstar_p : nullptr;
            if (l == 0)
                k_lstm_layer<768><<<gg, 256, GSM_BYTES>>>(
                    xin, hold, whi_p + WO0, wlo_p + WO0,
                    bcat_p, c_p, hnew, qdst, cnt_p + (s * 3) * 16);
            else
                k_lstm_layer<512><<<gg, 256, GSM_BYTES>>>(
                    xin, hold + (size_t)l * B_ * H_,
                    whi_p + woff[l], wlo_p + woff[l],
                    bcat_p + (size_t)l * 1024,
                    c_p + (size_t)l * B_ * H_,
                    hnew + (size_t)l * B_ * H_, qdst,
                    cnt_p + (s * 3 + l) * 16);
        }
        dim3 ag(B_, P_);
        k_attn_part<<<ag, 512>>>(hfeat_p, hnew + (size_t)2 * B_ * H_);
        k_attn_comb<<<B_, 256>>>(qstar_p);
    }
    k_out<<<B_, E_>>>(qstar_p, outW, outb, out);
}

// round 15
// speedup vs baseline: 1.2140x; 1.1880x over previous
#include <cuda_runtime.h>
#include <math.h>
#include <stdint.h>

#define D_ 256
#define H_ 256
#define B_ 128
#define E_ 128
#define STEPS_ 5
#define NMAX 100352
#define P_ 8            // attention partials per segment
#define ZK 4            // gates split-K factor
#define GP (B_ * 1024)

// ---------------- scratch ----------------
__device__ __align__(16) float g_hfeat[NMAX * H_];
__device__ __align__(16) float g_gpart[ZK * GP];
__device__ float g_hbuf[2][3][B_ * H_];
__device__ float g_c[3][B_ * H_];
__device__ float g_qstar[B_ * 2 * H_];
__device__ int   g_seg[B_ + 1];
__device__ __align__(16) float g_Wt1[D_ * H_];
__device__ __align__(16) float g_Wt2[H_ * H_];
__device__ float g_att_m[B_ * P_];
__device__ float g_att_d[B_ * P_];
__device__ __align__(16) float g_att_acc[B_ * P_ * H_];
__device__ __align__(16) float g_bcat[3][1024];
// gate-interleaved concatenated [Wih|Whh] hi/lo: row' = 4u+g
#define WO0 0
#define WO1 786432
#define WO2 1310720
#define WTOT 1835008
__device__ __align__(16) float g_Whi[WTOT];
__device__ __align__(16) float g_Wlo[WTOT];

__device__ __forceinline__ uint32_t cvt_tf32(float f) {
    uint32_t r;
    asm("cvt.rn.tf32.f32 %0, %1;" : "=r"(r) : "f"(f));
    return r;
}
__device__ __forceinline__ float sigf(float x) { return 1.f / (1.f + expf(-x)); }

#define CP16(dst, src) \
    asm volatile("cp.async.cg.shared.global [%0], [%1], 16;" :: "r"(dst), "l"(src) : "memory")
#define CPCOMMIT() asm volatile("cp.async.commit_group;" ::: "memory")
#define CPWAIT(n)  asm volatile("cp.async.wait_group %0;" :: "n"(n) : "memory")

#define MMA_TF32(d, a, b) \
    asm volatile( \
        "mma.sync.aligned.m16n8k8.row.col.f32.tf32.tf32.f32 " \
        "{%0,%1,%2,%3}, {%4,%5,%6,%7}, {%8,%9}, {%0,%1,%2,%3};" \
        : "+f"((d)[0]), "+f"((d)[1]), "+f"((d)[2]), "+f"((d)[3]) \
        : "r"((a)[0]), "r"((a)[1]), "r"((a)[2]), "r"((a)[3]), \
          "r"((b)[0]), "r"((b)[1]))

// ---------------- prep: seg + transpose + wsplit + bias + zero ---------------
__global__ __launch_bounds__(256) void k_prep(
    const int* __restrict__ bidx, int N,
    const float* __restrict__ W1, const float* __restrict__ W2,
    const float* __restrict__ Wih0, const float* __restrict__ Whh0,
    const float* __restrict__ Wih1, const float* __restrict__ Whh1,
    const float* __restrict__ Wih2, const float* __restrict__ Whh2,
    const float* __restrict__ bih0, const float* __restrict__ bhh0,
    const float* __restrict__ bih1, const float* __restrict__ bhh1,
    const float* __restrict__ bih2, const float* __restrict__ bhh2)
{
    const int b = blockIdx.x, tid = threadIdx.x;
    if (b == 0) {
        if (tid <= B_) {
            int lo = 0, hi = N;
            while (lo < hi) {
                int mid = (lo + hi) >> 1;
                if (bidx[mid] < tid) lo = mid + 1; else hi = mid;
            }
            g_seg[tid] = lo;
        }
    } else if (b <= 128) {
        __shared__ float t[32][33];
        int t2 = b - 1;
        const float* W = (t2 >= 64) ? W2 : W1;
        float* Wt = (t2 >= 64) ? g_Wt2 : g_Wt1;
        int tile = t2 & 63;
        int bx = (tile & 7) * 32, by = (tile >> 3) * 32;
        int tx = tid & 31, ty0 = tid >> 5;
#pragma unroll
        for (int i = 0; i < 4; i++) {
            int ty = ty0 + 8 * i;
            t[ty][tx] = W[(by + ty) * 256 + bx + tx];
        }
        __syncthreads();
#pragma unroll
        for (int i = 0; i < 4; i++) {
            int ty = ty0 + 8 * i;
            Wt[(bx + ty) * 256 + by + tx] = __uint_as_float(cvt_tf32(t[tx][ty]));
        }
    } else if (b <= 384) {
        int base = (b - 129) * 256 + tid;
        for (int i = base; i < WTOT; i += 65536) {
            int off, K; const float* Wih; const float* Whh;
            if (i < WO1)      { off = WO0; K = 768; Wih = Wih0; Whh = Whh0; }
            else if (i < WO2) { off = WO1; K = 512; Wih = Wih1; Whh = Whh1; }
            else              { off = WO2; K = 512; Wih = Wih2; Whh = Whh2; }
            int j = i - off;
            int n = j / K, k = j - n * K;
            int g = n & 3, u = n >> 2;
            int KW = K - 256;
            float v = (k < KW) ? Wih[(g * 256 + u) * KW + k]
                               : Whh[(g * 256 + u) * 256 + (k - KW)];
            float h = __uint_as_float(cvt_tf32(v));
            g_Whi[i] = h;
            g_Wlo[i] = __uint_as_float(cvt_tf32(v - h));
        }
    } else if (b <= 416) {
        int base = (b - 385) * 256 + tid;  // 8192 threads
        for (int i = base; i < B_ * 2 * H_; i += 8192) g_qstar[i] = 0.f;
        for (int i = base; i < 3 * B_ * H_; i += 8192) {
            g_hbuf[0][0][i] = 0.f;
            g_hbuf[1][0][i] = 0.f;
            g_c[0][i] = 0.f;
        }
    } else {
        for (int e = tid; e < 3 * 1024; e += 256) {
            int l = e >> 10, c = e & 1023, u = c >> 2, g = c & 3;
            const float* bi = (l == 0) ? bih0 : ((l == 1) ? bih1 : bih2);
            const float* bh = (l == 0) ? bhh0 : ((l == 1) ? bhh1 : bhh2);
            g_bcat[l][c] = bi[g * 256 + u] + bh[g * 256 + u];
        }
    }
}

// ---------------- fused FNN (R8 512-thread version, known good) --------------
#define FH 0
#define FSA 131072
#define FSB 163840
#define FSMEM 229376

__global__ __launch_bounds__(512) void k_fnn_fused(
    const float* __restrict__ X, const float* __restrict__ W1t,
    const float* __restrict__ W2t, const float* __restrict__ b1,
    const float* __restrict__ b2, float* __restrict__ Cout, int nrows)
{
    extern __shared__ char sm[];
    float* hbuf = (float*)(sm + FH);
    __shared__ float bias1[256];
    __shared__ float bias2[256];

    const int tid  = threadIdx.x;
    const int lane = tid & 31;
    const int warp = tid >> 5;
    const int wm = warp & 3;
    const int wn = warp >> 2;
    const int qr = lane >> 2;
    const int qc = lane & 3;
    const int row0 = blockIdx.x * 128;

    if (tid < 256) bias1[tid] = b1[tid];
    else           bias2[tid - 256] = b2[tid - 256];

    float acc[2][8][4];
#pragma unroll
    for (int mi = 0; mi < 2; mi++)
#pragma unroll
        for (int ni = 0; ni < 8; ni++)
#pragma unroll
            for (int j = 0; j < 4; j++) acc[mi][ni][j] = 0.f;

    auto stage1 = [&](int kc, int s) {
        char* dA = sm + FSA + s * 16384;
        char* dB = sm + FSB + s * 32768;
#pragma unroll
        for (int i = 0; i < 2; i++) {
            int gid = tid + 512 * i;
            int r = gid >> 3, g = gid & 7;
            int gr = row0 + r; if (gr >= nrows) gr = nrows - 1;
            uint32_t dst = (uint32_t)__cvta_generic_to_shared(
                dA + r * 128 + ((g ^ (r & 7)) << 4));
            CP16(dst, X + (size_t)gr * 256 + kc + g * 4);
        }
#pragma unroll
        for (int i = 0; i < 4; i++) {
            int gid = tid + 512 * i;
            int r = gid >> 3, g = gid & 7;
            uint32_t dst = (uint32_t)__cvta_generic_to_shared(
                dB + r * 128 + ((g ^ (r & 7)) << 4));
            CP16(dst, W1t + (size_t)r * 256 + kc + g * 4);
        }
        CPCOMMIT();
    };

    stage1(0, 0);
    for (int c = 0; c < 8; c++) {
        if (c + 1 < 8) { stage1((c + 1) * 32, (c + 1) & 1); CPWAIT(1); }
        else           { CPWAIT(0); }
        __syncthreads();
        const float* As = (const float*)(sm + FSA + (c & 1) * 16384);
        const float* Bs = (const float*)(sm + FSB + (c & 1) * 32768);
#pragma unroll
        for (int ks = 0; ks < 32; ks += 8) {
            const int g0 = ks >> 2;
            uint32_t af[2][4], bf[8][2];
#pragma unroll
            for (int mi = 0; mi < 2; mi++) {
                int ra = wm * 32 + mi * 16 + qr;
                int sw = (ra & 7);
                const float* pa  = As + ra * 32;
                const float* pa8 = pa + 8 * 32;
                af[mi][0] = __float_as_uint(pa [((g0 ^ sw) << 2) + qc]);
                af[mi][1] = __float_as_uint(pa8[((g0 ^ sw) << 2) + qc]);
                af[mi][2] = __float_as_uint(pa [(((g0 + 1) ^ sw) << 2) + qc]);
                af[mi][3] = __float_as_uint(pa8[(((g0 + 1) ^ sw) << 2) + qc]);
            }
#pragma unroll
            for (int ni = 0; ni < 8; ni++) {
                int rb = wn * 64 + ni * 8 + qr;
                int sw = (rb & 7);
                const float* pb = Bs + rb * 32;
                bf[ni][0] = __float_as_uint(pb[((g0 ^ sw) << 2) + qc]);
                bf[ni][1] = __float_as_uint(pb[(((g0 + 1) ^ sw) << 2) + qc]);
            }
#pragma unroll
            for (int mi = 0; mi < 2; mi++)
#pragma unroll
                for (int ni = 0; ni < 8; ni++) MMA_TF32(acc[mi][ni], af[mi], bf[ni]);
        }
        __syncthreads();
    }

#pragma unroll
    for (int mi = 0; mi < 2; mi++) {
        int r = wm * 32 + mi * 16 + qr;
        int sw = (r & 7);
#pragma unroll
        for (int ni = 0; ni < 8; ni++) {
            int cb = wn * 64 + ni * 8 + qc * 2;
            float b0 = bias1[cb], b1v = bias1[cb + 1];
            float v0 = acc[mi][ni][0] + b0, v1 = acc[mi][ni][1] + b1v;
            float v2 = acc[mi][ni][2] + b0, v3 = acc[mi][ni][3] + b1v;
            v0 = (v0 > 0.f) ? v0 : expm1f(v0);
            v1 = (v1 > 0.f) ? v1 : expm1f(v1);
            v2 = (v2 > 0.f) ? v2 : expm1f(v2);
            v3 = (v3 > 0.f) ? v3 : expm1f(v3);
            int gg = cb >> 2, go = cb & 3;
            float* hp  = hbuf + r * 256 + ((gg ^ sw) << 2) + go;
            float* hp8 = hp + 8 * 256;
            hp [0] = __uint_as_float(cvt_tf32(v0));
            hp [1] = __uint_as_float(cvt_tf32(v1));
            hp8[0] = __uint_as_float(cvt_tf32(v2));
            hp8[1] = __uint_as_float(cvt_tf32(v3));
            acc[mi][ni][0] = 0.f; acc[mi][ni][1] = 0.f;
            acc[mi][ni][2] = 0.f; acc[mi][ni][3] = 0.f;
        }
    }
    __syncthreads();

    auto stage2 = [&](int kc, int s) {
        char* dB = sm + FSB + s * 32768;
#pragma unroll
        for (int i = 0; i < 4; i++) {
            int gid = tid + 512 * i;
            int r = gid >> 3, g = gid & 7;
            uint32_t dst = (uint32_t)__cvta_generic_to_shared(
                dB + r * 128 + ((g ^ (r & 7)) << 4));
            CP16(dst, W2t + (size_t)r * 256 + kc + g * 4);
        }
        CPCOMMIT();
    };

    stage2(0, 0);
    for (int c = 0; c < 8; c++) {
        if (c + 1 < 8) { stage2((c + 1) * 32, (c + 1) & 1); CPWAIT(1); }
        else           { CPWAIT(0); }
        __syncthreads();
        const float* Bs = (const float*)(sm + FSB + (c & 1) * 32768);
#pragma unroll
        for (int ks = 0; ks < 32; ks += 8) {
            const int g0 = (c * 32 + ks) >> 2;
            const int g0l = ks >> 2;
            uint32_t af[2][4], bf[8][2];
#pragma unroll
            for (int mi = 0; mi < 2; mi++) {
                int ra = wm * 32 + mi * 16 + qr;
                int sw = (ra & 7);
                const float* pa  = hbuf + ra * 256;
                const float* pa8 = pa + 8 * 256;
                af[mi][0] = __float_as_uint(pa [((g0 ^ sw) << 2) + qc]);
                af[mi][1] = __float_as_uint(pa8[((g0 ^ sw) << 2) + qc]);
                af[mi][2] = __float_as_uint(pa [(((g0 + 1) ^ sw) << 2) + qc]);
                af[mi][3] = __float_as_uint(pa8[(((g0 + 1) ^ sw) << 2) + qc]);
            }
#pragma unroll
            for (int ni = 0; ni < 8; ni++) {
                int rb = wn * 64 + ni * 8 + qr;
                int sw = (rb & 7);
                const float* pb = Bs + rb * 32;
                bf[ni][0] = __float_as_uint(pb[((g0l ^ sw) << 2) + qc]);
                bf[ni][1] = __float_as_uint(pb[(((g0l + 1) ^ sw) << 2) + qc]);
            }
#pragma unroll
            for (int mi = 0; mi < 2; mi++)
#pragma unroll
                for (int ni = 0; ni < 8; ni++) MMA_TF32(acc[mi][ni], af[mi], bf[ni]);
        }
        __syncthreads();
    }

#pragma unroll
    for (int mi = 0; mi < 2; mi++) {
        int r0 = row0 + wm * 32 + mi * 16 + qr;
#pragma unroll
        for (int ni = 0; ni < 8; ni++) {
            int cb = wn * 64 + ni * 8 + qc * 2;
            float b0 = bias2[cb], b1v = bias2[cb + 1];
            if (r0 < nrows)
                *(float2*)(Cout + (size_t)r0 * 256 + cb) =
                    make_float2(acc[mi][ni][0] + b0, acc[mi][ni][1] + b1v);
            if (r0 + 8 < nrows)
                *(float2*)(Cout + (size_t)(r0 + 8) * 256 + cb) =
                    make_float2(acc[mi][ni][2] + b0, acc[mi][ni][3] + b1v);
        }
    }
}

// ---------------- LSTM gates via 3xTF32 HMMA (no fusion tail) ----------------
// Grid (16, ZK), 256 thr. Gate-interleaved cols; partials to g_gpart.
#define GSM_BYTES 98304

template <int K>
__global__ __launch_bounds__(256) void k_gates_mma(
    const float* __restrict__ xin, const float* __restrict__ hold,
    const float* __restrict__ Whi, const float* __restrict__ Wlo)
{
    extern __shared__ float gsm[];
    const int KW = K - 256;
    const int tid = threadIdx.x;
    const int lane = tid & 31, warp = tid >> 5;
    const int wm = warp & 1, wn = warp >> 1;
    const int qr = lane >> 2, qc = lane & 3;
    const int n0 = blockIdx.x * 64;
    const int z = blockIdx.y;
    const int kq = K >> 2;
    const int ko = z * kq;
    const int nc = kq >> 5;

    float acc[4][2][4];
#pragma unroll
    for (int mi = 0; mi < 4; mi++)
#pragma unroll
        for (int ni = 0; ni < 2; ni++)
#pragma unroll
            for (int j = 0; j < 4; j++) acc[mi][ni][j] = 0.f;

    float4 ra[4];
    auto ldgA = [&](int kglob) {
#pragma unroll
        for (int i = 0; i < 4; i++) {
            int gid = tid + 256 * i;
            int r = gid >> 3, g = gid & 7;
            int k = kglob + g * 4;
            const float* src; int stride, kk;
            if (k < KW) { src = xin;  stride = KW;  kk = k; }
            else        { src = hold; stride = 256; kk = k - KW; }
            ra[i] = *(const float4*)(src + (size_t)r * stride + kk);
        }
    };
    auto stsA = [&](int s) {
        float* Ahi = gsm + s * 12288;
        float* Alo = Ahi + 4096;
#pragma unroll
        for (int i = 0; i < 4; i++) {
            int gid = tid + 256 * i;
            int r = gid >> 3, g = gid & 7;
            int off = r * 32 + ((g ^ (r & 7)) << 2);
            float4 v = ra[i];
            float h0 = __uint_as_float(cvt_tf32(v.x));
            float h1 = __uint_as_float(cvt_tf32(v.y));
            float h2 = __uint_as_float(cvt_tf32(v.z));
            float h3 = __uint_as_float(cvt_tf32(v.w));
            Ahi[off + 0] = h0; Ahi[off + 1] = h1;
            Ahi[off + 2] = h2; Ahi[off + 3] = h3;
            Alo[off + 0] = __uint_as_float(cvt_tf32(v.x - h0));
            Alo[off + 1] = __uint_as_float(cvt_tf32(v.y - h1));
            Alo[off + 2] = __uint_as_float(cvt_tf32(v.z - h2));
            Alo[off + 3] = __uint_as_float(cvt_tf32(v.w - h3));
        }
    };
    auto stageB = [&](int kglob, int s) {
        float* Bhi = gsm + s * 12288 + 8192;
        float* Blo = gsm + s * 12288 + 10240;
#pragma unroll
        for (int i = 0; i < 4; i++) {
            int gid = tid + 256 * i;
            int hilo = gid >> 9;
            int rg = gid & 511;
            int r = rg >> 3, g = rg & 7;
            const float* src = (hilo ? Wlo : Whi) + (size_t)(n0 + r) * K + kglob + g * 4;
            float* dstb = hilo ? Blo : Bhi;
            uint32_t dst = (uint32_t)__cvta_generic_to_shared(
                dstb + r * 32 + ((g ^ (r & 7)) << 2));
            CP16(dst, src);
        }
        CPCOMMIT();
    };

    ldgA(ko);
    stageB(ko, 0);
    for (int ch = 0; ch < nc; ch++) {
        const int s = ch & 1;
        stsA(s);
        if (ch + 1 < nc) {
            ldgA(ko + (ch + 1) * 32);
            stageB(ko + (ch + 1) * 32, s ^ 1);
            CPWAIT(1);
        } else {
            CPWAIT(0);
        }
        __syncthreads();
        const float* Ahi = gsm + s * 12288;
        const float* Alo = Ahi + 4096;
        const float* Bhi = Ahi + 8192;
        const float* Blo = Ahi + 10240;
#pragma unroll
        for (int ks = 0; ks < 32; ks += 8) {
            const int g0 = ks >> 2;
            uint32_t ah[4][4], al[4][4], bh[2][2], bl[2][2];
#pragma unroll
            for (int mi = 0; mi < 4; mi++) {
                int rr = wm * 64 + mi * 16 + qr;
                int sw = (rr & 7);
                int o0 = rr * 32 + ((g0 ^ sw) << 2) + qc;
                int o1 = rr * 32 + (((g0 + 1) ^ sw) << 2) + qc;
                ah[mi][0] = __float_as_uint(Ahi[o0]);
                ah[mi][1] = __float_as_uint(Ahi[o0 + 256]);
                ah[mi][2] = __float_as_uint(Ahi[o1]);
                ah[mi][3] = __float_as_uint(Ahi[o1 + 256]);
                al[mi][0] = __float_as_uint(Alo[o0]);
                al[mi][1] = __float_as_uint(Alo[o0 + 256]);
                al[mi][2] = __float_as_uint(Alo[o1]);
                al[mi][3] = __float_as_uint(Alo[o1 + 256]);
            }
#pragma unroll
            for (int ni = 0; ni < 2; ni++) {
                int rb = wn * 16 + ni * 8 + qr;
                int sw = (rb & 7);
                int o0 = rb * 32 + ((g0 ^ sw) << 2) + qc;
                int o1 = rb * 32 + (((g0 + 1) ^ sw) << 2) + qc;
                bh[ni][0] = __float_as_uint(Bhi[o0]);
                bh[ni][1] = __float_as_uint(Bhi[o1]);
                bl[ni][0] = __float_as_uint(Blo[o0]);
                bl[ni][1] = __float_as_uint(Blo[o1]);
            }
#pragma unroll
            for (int mi = 0; mi < 4; mi++)
#pragma unroll
                for (int ni = 0; ni < 2; ni++) {
                    MMA_TF32(acc[mi][ni], ah[mi], bh[ni]);
                    MMA_TF32(acc[mi][ni], ah[mi], bl[ni]);
                    MMA_TF32(acc[mi][ni], al[mi], bh[ni]);
                }
        }
        __syncthreads();
    }

    float* gp = g_gpart + (size_t)z * GP;
#pragma unroll
    for (int mi = 0; mi < 4; mi++) {
        int r = wm * 64 + mi * 16 + qr;
#pragma unroll
        for (int ni = 0; ni < 2; ni++) {
            int colb = n0 + wn * 16 + ni * 8 + qc * 2;
            *(float2*)(gp + (size_t)r * 1024 + colb) =
                make_float2(acc[mi][ni][0], acc[mi][ni][1]);
            *(float2*)(gp + (size_t)(r + 8) * 1024 + colb) =
                make_float2(acc[mi][ni][2], acc[mi][ni][3]);
        }
    }
}

// ---------------- LSTM cell elementwise (interleaved float4 partials) --------
__global__ void k_update(const float* __restrict__ bcat,
                         float* __restrict__ c, float* __restrict__ hnew,
                         float* __restrict__ qdst)
{
    int r = blockIdx.x, u = threadIdx.x;   // 128 blocks x 256 threads
    int col = u * 4;
    float4 bv = *(const float4*)(bcat + col);
    float iv = bv.x, fv = bv.y, gv = bv.z, ov = bv.w;
#pragma unroll
    for (int z = 0; z < ZK; z++) {
        float4 pv = *(const float4*)(g_gpart + (size_t)z * GP + r * 1024 + col);
        iv += pv.x; fv += pv.y; gv += pv.z; ov += pv.w;
    }
    float cn = sigf(fv) * c[r * 256 + u] + sigf(iv) * tanhf(gv);
    c[r * 256 + u] = cn;
    float hn = sigf(ov) * tanhf(cn);
    hnew[r * 256 + u] = hn;
    if (qdst) qdst[r * 512 + u] = hn;
}

// ---------------- attention partials (R11, known good) -----------------------
__global__ __launch_bounds__(512) void k_attn_part(
    const float* __restrict__ hfeat, const float* __restrict__ q)
{
    const int b = blockIdx.x, part = blockIdx.y, tid = threadIdx.x;
    const int g0 = g_seg[b], g1 = g_seg[b + 1];
    const int len = g1 - g0;
    const int s0 = g0 + (int)(((long long)len * part) / P_);
    const int s1 = g0 + (int)(((long long)len * (part + 1)) / P_);

    __shared__ float q_s[256];
    __shared__ float e_s[2][128];
    __shared__ float ws[2][128];
    __shared__ float racc[256];
    __shared__ float red[16];
    if (tid < 256) q_s[tid] = q[b * 256 + tid];
    __syncthreads();

    const int lane = tid & 31, warp = tid >> 5;
    const int col = tid & 255, half = tid >> 8;
    float qreg[8];
#pragma unroll
    for (int k = 0; k < 8; k++) qreg[k] = q_s[lane + 32 * k];

    float acc = 0.f, dpart = 0.f, m = -INFINITY;
    int buf = 0;

    for (int c0 = s0; c0 < s1; c0 += 128, buf ^= 1) {
        const int cnt = min(128, s1 - c0);
#pragma unroll
        for (int i = 0; i < 8; i++) {
            int nl = warp * 8 + i;
            if (nl < cnt) {
                const float* hr = hfeat + (size_t)(c0 + nl) * 256;
                float p = 0.f;
#pragma unroll
                for (int k = 0; k < 8; k++) p += hr[lane + 32 * k] * qreg[k];
#pragma unroll
                for (int off = 16; off; off >>= 1) p += __shfl_xor_sync(0xffffffffu, p, off);
                if (lane == 0) e_s[buf][nl] = p;
            }
        }
        __syncthreads();
        float v = -INFINITY;
#pragma unroll
        for (int j = 0; j < 4; j++) {
            int idx = lane + 32 * j;
            if (idx < cnt) v = fmaxf(v, e_s[buf][idx]);
        }
#pragma unroll
        for (int off = 16; off; off >>= 1)
            v = fmaxf(v, __shfl_xor_sync(0xffffffffu, v, off));
        const float mnew = fmaxf(m, v);
        const float scale = expf(m - mnew);
        acc *= scale; dpart *= scale; m = mnew;
        if (tid < cnt) {
            float wv = expf(e_s[buf][tid] - mnew);
            ws[buf][tid] = wv;
            dpart += wv;
        }
        __syncthreads();
        const int i0 = half * 64;
        const int i1 = min(cnt, i0 + 64);
        const float* bp = hfeat + ((size_t)c0 + i0) * 256 + col;
        const float* wp = ws[buf] + i0;
        if (i1 - i0 == 64) {
            float t0 = 0.f, t1 = 0.f, t2 = 0.f, t3 = 0.f;
#pragma unroll
            for (int i = 0; i < 64; i += 4) {
                t0 += wp[i]     * bp[(size_t)i * 256];
                t1 += wp[i + 1] * bp[(size_t)(i + 1) * 256];
                t2 += wp[i + 2] * bp[(size_t)(i + 2) * 256];
                t3 += wp[i + 3] * bp[(size_t)(i + 3) * 256];
            }
            acc += (t0 + t1) + (t2 + t3);
        } else {
            for (int i = 0; i < i1 - i0; i++) acc += wp[i] * bp[(size_t)i * 256];
        }
    }

    float d = dpart;
#pragma unroll
    for (int off = 16; off; off >>= 1) d += __shfl_xor_sync(0xffffffffu, d, off);
    if (lane == 0) red[warp] = d;
    if (half == 0) racc[col] = acc;
    __syncthreads();
    const int idx = b * P_ + part;
    if (tid == 0) {
        float s = 0.f;
        for (int i = 0; i < 16; i++) s += red[i];
        g_att_d[idx] = s;
        g_att_m[idx] = m;
    }
    if (half == 1) g_att_acc[(size_t)idx * 256 + col] = racc[col] + acc;
}

// ---------------- attention combine ----------------
__global__ __launch_bounds__(256) void k_attn_comb(float* __restrict__ qstar)
{
    const int b = blockIdx.x, col = threadIdx.x;
    __shared__ float sc[P_];
    __shared__ float sdenom;
    if (col == 0) {
        float m = -INFINITY;
#pragma unroll
        for (int p = 0; p < P_; p++) m = fmaxf(m, g_att_m[b * P_ + p]);
        if (!isfinite(m)) m = 0.f;
        float denom = 0.f;
#pragma unroll
        for (int p = 0; p < P_; p++) {
            float e = expf(g_att_m[b * P_ + p] - m);
            sc[p] = e;
            denom += g_att_d[b * P_ + p] * e;
        }
        sdenom = denom + 1e-16f;
    }
    __syncthreads();
    float r = 0.f;
#pragma unroll
    for (int p = 0; p < P_; p++)
        r += sc[p] * g_att_acc[(size_t)(b * P_ + p) * 256 + col];
    qstar[b * 2 * H_ + 256 + col] = r / sdenom;
}

// ---------------- output projection ----------------
__global__ void k_out(const float* __restrict__ qstar, const float* __restrict__ W,
                      const float* __restrict__ bias, float* __restrict__ out)
{
    int b = blockIdx.x, e = threadIdx.x;
    __shared__ float qs[512];
    qs[e] = qstar[b * 512 + e];
    qs[e + 128] = qstar[b * 512 + e + 128];
    qs[e + 256] = qstar[b * 512 + e + 256];
    qs[e + 384] = qstar[b * 512 + e + 384];
    __syncthreads();
    float acc = bias[e];
#pragma unroll 8
    for (int k = 0; k < 512; k++) acc += qs[k] * W[k * E_ + e];
    out[b * E_ + e] = acc;
}

// ---------------- launch ----------------
extern "C" void kernel_launch(void* const* d_in, const int* in_sizes, int n_in,
                              void* d_out, int out_size)
{
    const float* x    = (const float*)d_in[0];
    const int*   bidx = (const int*)d_in[1];
    const float* W1   = (const float*)d_in[2];
    const float* b1   = (const float*)d_in[3];
    const float* W2   = (const float*)d_in[4];
    const float* b2   = (const float*)d_in[5];
    const float* outW = (const float*)d_in[18];
    const float* outb = (const float*)d_in[19];
    float* out = (float*)d_out;

    const int N = in_sizes[0] / D_;

    float *hfeat_p, *hbuf_p, *c_p, *qstar_p, *wt1_p, *wt2_p, *whi_p, *wlo_p, *bcat_p;
    cudaGetSymbolAddress((void**)&hfeat_p, g_hfeat);
    cudaGetSymbolAddress((void**)&hbuf_p,  g_hbuf);
    cudaGetSymbolAddress((void**)&c_p,     g_c);
    cudaGetSymbolAddress((void**)&qstar_p, g_qstar);
    cudaGetSymbolAddress((void**)&wt1_p,   g_Wt1);
    cudaGetSymbolAddress((void**)&wt2_p,   g_Wt2);
    cudaGetSymbolAddress((void**)&whi_p,   g_Whi);
    cudaGetSymbolAddress((void**)&wlo_p,   g_Wlo);
    cudaGetSymbolAddress((void**)&bcat_p,  g_bcat);

    cudaFuncSetAttribute(k_fnn_fused, cudaFuncAttributeMaxDynamicSharedMemorySize, FSMEM);
    cudaFuncSetAttribute(k_gates_mma<768>, cudaFuncAttributeMaxDynamicSharedMemorySize, GSM_BYTES);
    cudaFuncSetAttribute(k_gates_mma<512>, cudaFuncAttributeMaxDynamicSharedMemorySize, GSM_BYTES);

    k_prep<<<418, 256>>>(bidx, N, W1, W2,
                         (const float*)d_in[6],  (const float*)d_in[7],
                         (const float*)d_in[10], (const float*)d_in[11],
                         (const float*)d_in[14], (const float*)d_in[15],
                         (const float*)d_in[8],  (const float*)d_in[9],
                         (const float*)d_in[12], (const float*)d_in[13],
                         (const float*)d_in[16], (const float*)d_in[17]);

    k_fnn_fused<<<(N + 127) / 128, 512, FSMEM>>>(x, wt1_p, wt2_p, b1, b2, hfeat_p, N);

    const int woff[3] = {WO0, WO1, WO2};
    for (int s = 0; s < STEPS_; s++) {
        float* hold = hbuf_p + (size_t)(s & 1) * 3 * B_ * H_;
        float* hnew = hbuf_p + (size_t)((s & 1) ^ 1) * 3 * B_ * H_;
        for (int l = 0; l < 3; l++) {
            const float* xin = (l == 0) ? (const float*)qstar_p
                                        : (const float*)(hnew + (size_t)(l - 1) * B_ * H_);
            dim3 gg(16, ZK);
            if (l == 0)
                k_gates_mma<768><<<gg, 256, GSM_BYTES>>>(
                    xin, hold, whi_p + WO0, wlo_p + WO0);
            else
                k_gates_mma<512><<<gg, 256, GSM_BYTES>>>(
                    xin, hold + (size_t)l * B_ * H_,
                    whi_p + woff[l], wlo_p + woff[l]);
            k_update<<<B_, H_>>>(bcat_p + (size_t)l * 1024,
                                 c_p + (size_t)l * B_ * H_,
                                 hnew + (size_t)l * B_ * H_,
                                 (l == 2) ? qstar_p : nullptr);
        }
        dim3 ag(B_, P_);
        k_attn_part<<<ag, 512>>>(hfeat_p, hnew + (size_t)2 * B_ * H_);
        k_attn_comb<<<B_, 256>>>(qstar_p);
    }
    k_out<<<B_, E_>>>(qstar_p, outW, outb, out);
}